// round 8
// baseline (speedup 1.0000x reference)
#include <cuda_runtime.h>

#define NPTS    8192
#define BATCH   4
#define NPOINT  2048
#define NSAMPLE 32
#define CIN     67
#define COUT    128
#define KTOT    (CIN * NSAMPLE)   // 2144
#define R2      0.04f

#define TPB     512

// FPS: 4 CTAs (one cluster) per batch
#define FPS_CTAS 16               // 4 batches x 4 ranks
#define QPTS    2048              // points per FPS CTA
#define FPPT    (QPTS / TPB)      // 4 points per thread
#define FNPAIR  (FPPT / 2)        // 2 packed pairs

#define WPB     32                // worker CTAs per batch
#define NWORK   (WPB * BATCH)     // 128 workers
#define TILE    16                // centers per steady-state conv tile
#define TILES16 120               // 16-center tiles per batch (centers 0..1920)
#define MINI_BASE 1920            // final 128 centers -> 32 minitiles of 4
#define NMINI   32
#define WPAD    132               // s_w row pitch (132 % 32 == 4 -> conflict-free)

typedef unsigned long long ull;

// progress flags: one 128B line per batch
__device__ int g_progress[BATCH * 32];

// ---------------------------------------------------------------------------
// packed f32x2 helpers (sm_103a) — add/sub/mul only
// ---------------------------------------------------------------------------
__device__ __forceinline__ ull f2pk(float lo, float hi) {
    ull r; asm("mov.b64 %0, {%1, %2};" : "=l"(r) : "f"(lo), "f"(hi)); return r;
}
__device__ __forceinline__ void f2unpk(ull v, float& lo, float& hi) {
    asm("mov.b64 {%0, %1}, %2;" : "=f"(lo), "=f"(hi) : "l"(v));
}
__device__ __forceinline__ ull f2add(ull a, ull b) {
    ull r; asm("add.rn.f32x2 %0, %1, %2;" : "=l"(r) : "l"(a), "l"(b)); return r;
}
__device__ __forceinline__ ull f2sub(ull a, ull b) {
    ull r; asm("sub.rn.f32x2 %0, %1, %2;" : "=l"(r) : "l"(a), "l"(b)); return r;
}
__device__ __forceinline__ ull f2mul(ull a, ull b) {
    ull r; asm("mul.rn.f32x2 %0, %1, %2;" : "=l"(r) : "l"(a), "l"(b)); return r;
}

// ---------------------------------------------------------------------------
// cluster / mbarrier helpers
// ---------------------------------------------------------------------------
__device__ __forceinline__ unsigned smem_u32(const void* p) {
    unsigned a;
    asm("{ .reg .u64 t; cvta.to.shared.u64 t, %1; cvt.u32.u64 %0, t; }"
        : "=r"(a) : "l"(p));
    return a;
}
__device__ __forceinline__ unsigned mapa_rank(unsigned addr, unsigned r) {
    unsigned d;
    asm("mapa.shared::cluster.u32 %0, %1, %2;" : "=r"(d) : "r"(addr), "r"(r));
    return d;
}
__device__ __forceinline__ void dsmem_st_u64(unsigned addr, ull v) {
    asm volatile("st.shared::cluster.u64 [%0], %1;" :: "r"(addr), "l"(v) : "memory");
}
__device__ __forceinline__ void mbar_init(unsigned addr, unsigned cnt) {
    asm volatile("mbarrier.init.shared.b64 [%0], %1;" :: "r"(addr), "r"(cnt) : "memory");
}
__device__ __forceinline__ void mbar_arrive_cluster(unsigned addr) {
    asm volatile("mbarrier.arrive.release.cluster.shared::cluster.b64 _, [%0];"
                 :: "r"(addr) : "memory");
}
__device__ __forceinline__ void mbar_wait(unsigned addr, unsigned parity) {
    unsigned done;
    do {
        asm volatile("{\n\t.reg .pred p;\n\t"
                     "mbarrier.try_wait.parity.acquire.cluster.shared::cta.b64 p, [%1], %2;\n\t"
                     "selp.b32 %0, 1, 0, p;\n\t}"
                     : "=r"(done) : "r"(addr), "r"(parity) : "memory");
    } while (!done);
}
__device__ __forceinline__ void cluster_barrier() {
    asm volatile("barrier.cluster.arrive.aligned;" ::: "memory");
    asm volatile("barrier.cluster.wait.aligned;" ::: "memory");
}

__global__ void reset_kernel() {
    if (threadIdx.x < BATCH * 32) g_progress[threadIdx.x] = 0;
}

// ---------------------------------------------------------------------------
// worker helpers
// ---------------------------------------------------------------------------
__device__ __forceinline__ void wait_progress(const int* flag, int target) {
    if (threadIdx.x == 0) {
        unsigned pr;
        while (true) {
            asm volatile("ld.acquire.gpu.global.u32 %0, [%1];"
                         : "=r"(pr) : "l"(flag) : "memory");
            if ((int)pr >= target) break;
            __nanosleep(256);
        }
    }
    __syncthreads();
}

__device__ __forceinline__ void ball_one(const float* __restrict__ P,
                                         const float* __restrict__ nx,
                                         size_t crow, int lane,
                                         int* row, float* ctr3)
{
    const float cx = nx[crow + 0];
    const float cy = nx[crow + 1];
    const float cz = nx[crow + 2];
    if (lane < 3) ctr3[lane] = nx[crow + lane];

    int filled = 0, first = 0;
    for (int basei = 0; basei < NPTS; basei += 32) {
        const int i = basei + lane;
        float dx = __fadd_rn(P[i * 3 + 0], -cx);
        float dy = __fadd_rn(P[i * 3 + 1], -cy);
        float dz = __fadd_rn(P[i * 3 + 2], -cz);
        float d2 = __fadd_rn(__fadd_rn(__fmul_rn(dx, dx), __fmul_rn(dy, dy)),
                             __fmul_rn(dz, dz));
        unsigned m = __ballot_sync(0xffffffffu, d2 < R2);
        if (filled == 0 && m) first = basei + __ffs(m) - 1;
        if (d2 < R2) {
            int pos = filled + __popc(m & ((1u << lane) - 1));
            if (pos < NSAMPLE) row[pos] = i;
        }
        filled += __popc(m);
        if (filled >= NSAMPLE) break;
    }
    for (int j = filled + lane; j < NSAMPLE; j += 32) row[j] = first;
}

// ---------------------------------------------------------------------------
// Fused persistent kernel, cluster dims (4,1,1).
// Blocks 0..15: FPS, cluster c = batch c (ranks 0..3 each own 2048 points).
// Blocks 16..143: workers (32 per batch), same scheme as before.
// ---------------------------------------------------------------------------
__global__ void __launch_bounds__(TPB, 1) __cluster_dims__(4, 1, 1)
fused_kernel(const float* __restrict__ points,
             const float* __restrict__ features,
             const float* __restrict__ weight,
             float* __restrict__ new_xyz,
             float* __restrict__ conv_out)
{
    extern __shared__ char smraw[];
    __shared__ ull redw[2][TPB / 32];
    __shared__ ull slots[2][4];       // [parity][rank] candidates
    __shared__ ull mbar[2];           // parity-double-buffered mbarriers

    const int t = threadIdx.x;
    const int lane = t & 31;
    const int w = t >> 5;

    if (blockIdx.x < FPS_CTAS) {
        // ======================= FPS role =======================
        const int b = blockIdx.x >> 2;
        const unsigned rank = blockIdx.x & 3;
        float4* pts4 = (float4*)smraw;           // full NPTS copy, 128 KB
        const float* P = points + (size_t)b * NPTS * 3;

        for (int i = t; i < NPTS; i += TPB)
            pts4[i] = make_float4(P[3 * i], P[3 * i + 1], P[3 * i + 2], 0.0f);
        if (t == 0) {
            mbar_init(smem_u32(&mbar[0]), 4);
            mbar_init(smem_u32(&mbar[1]), 4);
        }
        __syncthreads();
        cluster_barrier();   // all 4 ranks: mbars init'd + pts loaded

        // writer lanes (warp 0, lanes 0..3): precompute remote addresses
        unsigned r_slot[2], r_mbar[2];
        if (w == 0 && lane < 4) {
            const unsigned dst = lane;
            r_slot[0] = mapa_rank(smem_u32(&slots[0][rank]), dst);
            r_slot[1] = mapa_rank(smem_u32(&slots[1][rank]), dst);
            r_mbar[0] = mapa_rank(smem_u32(&mbar[0]), dst);
            r_mbar[1] = mapa_rank(smem_u32(&mbar[1]), dst);
        }
        const unsigned l_mbar0 = smem_u32(&mbar[0]);
        const unsigned l_mbar1 = smem_u32(&mbar[1]);
        unsigned ph[2] = {0u, 0u};

        const int base = rank * QPTS + t * FPPT;
        ull px2[FNPAIR], py2[FNPAIR], pz2[FNPAIR];
        float dist[FPPT];
#pragma unroll
        for (int j = 0; j < FNPAIR; j++) {
            float4 a = pts4[base + 2 * j];
            float4 c = pts4[base + 2 * j + 1];
            px2[j] = f2pk(a.x, c.x);
            py2[j] = f2pk(a.y, c.y);
            pz2[j] = f2pk(a.z, c.z);
        }
#pragma unroll
        for (int j = 0; j < FPPT; j++) dist[j] = 1e10f;

        float4 q0 = pts4[0];
        float lx = q0.x, ly = q0.y, lz = q0.z;
        if (rank == 0 && t == 0) {
            float* o = new_xyz + (size_t)b * NPOINT * 3;
            o[0] = lx; o[1] = ly; o[2] = lz;
        }

        for (int iter = 1; iter < NPOINT; ++iter) {
            const int par = iter & 1;
            const ull lxp = f2pk(lx, lx);
            const ull lyp = f2pk(ly, ly);
            const ull lzp = f2pk(lz, lz);

            float bv = -1.0f;
#pragma unroll
            for (int j = 0; j < FNPAIR; j++) {
                // identical arithmetic to reference: (dx*dx+dy*dy)+dz*dz, rn
                ull dx = f2sub(px2[j], lxp);
                ull dy = f2sub(py2[j], lyp);
                ull dz = f2sub(pz2[j], lzp);
                ull d2 = f2add(f2add(f2mul(dx, dx), f2mul(dy, dy)), f2mul(dz, dz));
                float d0, d1;
                f2unpk(d2, d0, d1);
                float n0 = fminf(dist[2 * j + 0], d0);
                float n1 = fminf(dist[2 * j + 1], d1);
                dist[2 * j + 0] = n0;
                dist[2 * j + 1] = n1;
                bv = fmaxf(bv, fmaxf(n0, n1));
            }

            // ---- local block reduce (same as proven R3 scheme) ----
            const unsigned bb = __float_as_uint(bv);
            const unsigned wm = __reduce_max_sync(0xffffffffu, bb);
            unsigned li = 0x7fffffffu;
            if (bb == wm) {
#pragma unroll
                for (int j = FPPT - 1; j >= 0; j--)
                    if (__float_as_uint(dist[j]) == wm) li = base + j;
            }
            const unsigned wi_ = __reduce_min_sync(0xffffffffu, li);
            if (lane == 0)
                redw[par][w] = ((ull)wm << 32) | wi_;
            __syncthreads();

            const ull v = (lane < TPB / 32) ? redw[par][lane] : 0ull;
            const unsigned hv = (unsigned)(v >> 32);
            const unsigned lv = (unsigned)v;
            const unsigned gmv = __reduce_max_sync(0xffffffffu, hv);
            const unsigned ii = (hv == gmv) ? lv : 0x7fffffffu;
            const unsigned lbest = __reduce_min_sync(0xffffffffu, ii);

            // ---- cross-CTA exchange (DSMEM all-to-all) ----
            // pack: higher val wins; equal val -> larger (8191-idx) = lower idx
            const ull packed = ((ull)gmv << 32) | (unsigned)(8191 - lbest);
            if (w == 0 && lane < 4) {
                dsmem_st_u64(r_slot[par], packed);
                mbar_arrive_cluster(r_mbar[par]);
            }
            mbar_wait(par ? l_mbar1 : l_mbar0, ph[par]);
            ph[par] ^= 1u;

            ull m0 = slots[par][0], m1 = slots[par][1];
            ull m2 = slots[par][2], m3 = slots[par][3];
            ull mm = max(max(m0, m1), max(m2, m3));
            const int best = 8191 - (int)(unsigned)mm;

            float4 q = pts4[best];
            lx = q.x; ly = q.y; lz = q.z;
            if (rank == 0 && t == 0) {
                float* o = new_xyz + ((size_t)b * NPOINT + iter) * 3;
                o[0] = lx; o[1] = ly; o[2] = lz;
                if ((iter & 31) == 31)
                    asm volatile("st.release.gpu.global.u32 [%0], %1;"
                                 :: "l"(g_progress + b * 32), "r"(iter + 1) : "memory");
            }
        }
        cluster_barrier();   // keep smem alive until all ranks done
    } else {
        // ======================= worker role =======================
        const int wi = blockIdx.x - FPS_CTAS;    // 0..NWORK-1
        const int b = wi >> 5;
        const int wslot = wi & 31;

        float* s_g   = (float*)smraw;                   // [16][128]
        float* s_w   = s_g + TILE * 128;                // [128][WPAD]
        int*   s_idx = (int*)(s_w + COUT * WPAD);       // [16][32]
        float* s_ctr = (float*)(s_idx + TILE * NSAMPLE);// [16][3]

        const float*  P  = points + (size_t)b * NPTS * 3;
        const float4* F4 = (const float4*)(features + (size_t)b * NPTS * 64);
        const int* flag = g_progress + b * 32;

        // ---------- steady state: 16-center tiles, round-robin ----------
        for (int tile = wslot; tile < TILES16; tile += WPB) {
            const int p0 = tile * TILE;
            wait_progress(flag, p0 + TILE);

            ball_one(P, new_xyz, ((size_t)b * NPOINT + p0 + w) * 3, lane,
                     s_idx + w * NSAMPLE, s_ctr + w * 3);
            __syncthreads();

            const int og = lane;
            const int pg = w;
            const int myidx = s_idx[pg * NSAMPLE + lane];

            float acc[4] = {0.0f, 0.0f, 0.0f, 0.0f};
            for (int chunk = 0; chunk < 17; chunk++) {
                const int c0   = (chunk == 0) ? 0 : (4 * chunk - 1);
                const int kend = (chunk == 0) ? 96 : 128;
                __syncthreads();

                if (chunk == 0) {
#pragma unroll
                    for (int ci = 0; ci < 3; ci++)
                        s_g[pg * 128 + ci * 32 + lane] =
                            P[myidx * 3 + ci] - s_ctr[pg * 3 + ci];
                } else {
                    float4 fv = F4[(size_t)myidx * 16 + (chunk - 1)];
                    s_g[pg * 128 +  0 + lane] = fv.x;
                    s_g[pg * 128 + 32 + lane] = fv.y;
                    s_g[pg * 128 + 64 + lane] = fv.z;
                    s_g[pg * 128 + 96 + lane] = fv.w;
                }
#pragma unroll
                for (int q = 0; q < 8; q++) {
                    const int task = q * TPB + t;
                    const int o = task >> 5;
                    const int k4 = (task & 31) * 4;
                    if (k4 < kend)
                        *(float4*)&s_w[o * WPAD + k4] =
                            *(const float4*)(weight + (size_t)o * KTOT + c0 * 32 + k4);
                }
                __syncthreads();

                for (int kk = 0; kk < kend; kk += 4) {
                    float4 w0 = *(const float4*)&s_w[(og +  0) * WPAD + kk];
                    float4 w1 = *(const float4*)&s_w[(og + 32) * WPAD + kk];
                    float4 w2 = *(const float4*)&s_w[(og + 64) * WPAD + kk];
                    float4 w3 = *(const float4*)&s_w[(og + 96) * WPAD + kk];
                    float4 g  = *(const float4*)&s_g[pg * 128 + kk];
                    acc[0] = fmaf(g.x, w0.x, fmaf(g.y, w0.y, fmaf(g.z, w0.z, fmaf(g.w, w0.w, acc[0]))));
                    acc[1] = fmaf(g.x, w1.x, fmaf(g.y, w1.y, fmaf(g.z, w1.z, fmaf(g.w, w1.w, acc[1]))));
                    acc[2] = fmaf(g.x, w2.x, fmaf(g.y, w2.y, fmaf(g.z, w2.z, fmaf(g.w, w2.w, acc[2]))));
                    acc[3] = fmaf(g.x, w3.x, fmaf(g.y, w3.y, fmaf(g.z, w3.z, fmaf(g.w, w3.w, acc[3]))));
                }
            }

            float* dst = conv_out + ((size_t)b * NPOINT + p0 + pg) * COUT;
            dst[og +  0] = acc[0];
            dst[og + 32] = acc[1];
            dst[og + 64] = acc[2];
            dst[og + 96] = acc[3];
            __syncthreads();
        }

        // ---------- tail: one 4-center minitile per worker ----------
        if (wslot < NMINI) {
            const int p0 = MINI_BASE + wslot * 4;
            wait_progress(flag, p0 + 4);

            if (w < 4)
                ball_one(P, new_xyz, ((size_t)b * NPOINT + p0 + w) * 3, lane,
                         s_idx + w * NSAMPLE, s_ctr + w * 3);
            __syncthreads();

            const int o = t & 127;          // one output per thread
            const int p = t >> 7;           // one point per thread
            const int myidx = (t < 128) ? s_idx[(t >> 5) * NSAMPLE + lane] : 0;

            float acc = 0.0f;
            for (int chunk = 0; chunk < 17; chunk++) {
                const int c0   = (chunk == 0) ? 0 : (4 * chunk - 1);
                const int kend = (chunk == 0) ? 96 : 128;
                __syncthreads();

                if (t < 128) {
                    const int pp = t >> 5;
                    if (chunk == 0) {
#pragma unroll
                        for (int ci = 0; ci < 3; ci++)
                            s_g[pp * 128 + ci * 32 + lane] =
                                P[myidx * 3 + ci] - s_ctr[pp * 3 + ci];
                    } else {
                        float4 fv = F4[(size_t)myidx * 16 + (chunk - 1)];
                        s_g[pp * 128 +  0 + lane] = fv.x;
                        s_g[pp * 128 + 32 + lane] = fv.y;
                        s_g[pp * 128 + 64 + lane] = fv.z;
                        s_g[pp * 128 + 96 + lane] = fv.w;
                    }
                }
#pragma unroll
                for (int q = 0; q < 8; q++) {
                    const int task = q * TPB + t;
                    const int oo = task >> 5;
                    const int k4 = (task & 31) * 4;
                    if (k4 < kend)
                        *(float4*)&s_w[oo * WPAD + k4] =
                            *(const float4*)(weight + (size_t)oo * KTOT + c0 * 32 + k4);
                }
                __syncthreads();

                for (int kk = 0; kk < kend; kk += 4) {
                    float4 wv = *(const float4*)&s_w[o * WPAD + kk];
                    float4 g  = *(const float4*)&s_g[p * 128 + kk];
                    acc = fmaf(g.x, wv.x, fmaf(g.y, wv.y, fmaf(g.z, wv.z, fmaf(g.w, wv.w, acc))));
                }
            }
            conv_out[((size_t)b * NPOINT + p0 + p) * COUT + o] = acc;
        }
    }
}

// ---------------------------------------------------------------------------

extern "C" void kernel_launch(void* const* d_in, const int* in_sizes, int n_in,
                              void* d_out, int out_size)
{
    const float* points   = (const float*)d_in[0];
    const float* features = (const float*)d_in[1];
    const float* weight   = (const float*)d_in[2];
    float* out = (float*)d_out;
    float* new_xyz = out;                            // B*NPOINT*3
    float* conv    = out + BATCH * NPOINT * 3;       // B*NPOINT*COUT

    const int smem = NPTS * sizeof(float4);          // 128 KB
    cudaFuncSetAttribute(fused_kernel, cudaFuncAttributeMaxDynamicSharedMemorySize, smem);

    reset_kernel<<<1, 128>>>();
    fused_kernel<<<FPS_CTAS + NWORK, TPB, smem>>>(points, features, weight, new_xyz, conv);
}

// round 9
// speedup vs baseline: 1.4247x; 1.4247x over previous
#include <cuda_runtime.h>

#define NPTS    8192
#define BATCH   4
#define NPOINT  2048
#define NSAMPLE 32
#define CIN     67
#define COUT    128
#define KTOT    (CIN * NSAMPLE)   // 2144
#define R2      0.04f

#define TPB     512

// FPS: 4 CTAs (one cluster) per batch
#define FPS_CTAS 16               // 4 batches x 4 ranks
#define QPTS    2048              // points per FPS rank
#define FPPT    (QPTS / TPB)      // 4 points per thread
#define FNPAIR  (FPPT / 2)        // 2 packed pairs

#define WPB     28                // worker CTAs per batch
#define NWORK   (WPB * BATCH)     // 112 workers (total grid 128 <= 132 cap)
#define TILE    16                // centers per steady-state conv tile
#define TILES16 121               // 16-center tiles per batch (centers 0..1936)
#define MINI_BASE 1936            // final 112 centers -> 28 minitiles of 4
#define NMINI   28
#define WPAD    132               // s_w row pitch (132 % 32 == 4 -> conflict-free)

typedef unsigned long long ull;

// progress flags: one 128B line per batch
__device__ int g_progress[BATCH * 32];

// ---------------------------------------------------------------------------
// packed f32x2 helpers (sm_103a) — add/sub/mul only
// ---------------------------------------------------------------------------
__device__ __forceinline__ ull f2pk(float lo, float hi) {
    ull r; asm("mov.b64 %0, {%1, %2};" : "=l"(r) : "f"(lo), "f"(hi)); return r;
}
__device__ __forceinline__ void f2unpk(ull v, float& lo, float& hi) {
    asm("mov.b64 {%0, %1}, %2;" : "=f"(lo), "=f"(hi) : "l"(v));
}
__device__ __forceinline__ ull f2add(ull a, ull b) {
    ull r; asm("add.rn.f32x2 %0, %1, %2;" : "=l"(r) : "l"(a), "l"(b)); return r;
}
__device__ __forceinline__ ull f2sub(ull a, ull b) {
    ull r; asm("sub.rn.f32x2 %0, %1, %2;" : "=l"(r) : "l"(a), "l"(b)); return r;
}
__device__ __forceinline__ ull f2mul(ull a, ull b) {
    ull r; asm("mul.rn.f32x2 %0, %1, %2;" : "=l"(r) : "l"(a), "l"(b)); return r;
}
__device__ __forceinline__ ull umax64(ull a, ull b) { return a > b ? a : b; }

// ---------------------------------------------------------------------------
// cluster helpers (no mbarriers — tagged-slot polling instead)
// ---------------------------------------------------------------------------
__device__ __forceinline__ unsigned smem_u32(const void* p) {
    unsigned a;
    asm("{ .reg .u64 t; cvta.to.shared.u64 t, %1; cvt.u32.u64 %0, t; }"
        : "=r"(a) : "l"(p));
    return a;
}
__device__ __forceinline__ unsigned mapa_rank(unsigned addr, unsigned r) {
    unsigned d;
    asm("mapa.shared::cluster.u32 %0, %1, %2;" : "=r"(d) : "r"(addr), "r"(r));
    return d;
}
__device__ __forceinline__ void dsmem_st_u64(unsigned addr, ull v) {
    asm volatile("st.shared::cluster.u64 [%0], %1;" :: "r"(addr), "l"(v) : "memory");
}
__device__ __forceinline__ void cluster_barrier() {
    asm volatile("barrier.cluster.arrive.aligned;" ::: "memory");
    asm volatile("barrier.cluster.wait.aligned;" ::: "memory");
}

__global__ void reset_kernel() {
    if (threadIdx.x < BATCH * 32) g_progress[threadIdx.x] = 0;
}

// ---------------------------------------------------------------------------
// worker helpers
// ---------------------------------------------------------------------------
__device__ __forceinline__ void wait_progress(const int* flag, int target) {
    if (threadIdx.x == 0) {
        unsigned pr;
        while (true) {
            asm volatile("ld.acquire.gpu.global.u32 %0, [%1];"
                         : "=r"(pr) : "l"(flag) : "memory");
            if ((int)pr >= target) break;
            __nanosleep(256);
        }
    }
    __syncthreads();
}

__device__ __forceinline__ void ball_one(const float* __restrict__ P,
                                         const float* __restrict__ nx,
                                         size_t crow, int lane,
                                         int* row, float* ctr3)
{
    const float cx = nx[crow + 0];
    const float cy = nx[crow + 1];
    const float cz = nx[crow + 2];
    if (lane < 3) ctr3[lane] = nx[crow + lane];

    int filled = 0, first = 0;
    for (int basei = 0; basei < NPTS; basei += 32) {
        const int i = basei + lane;
        float dx = __fadd_rn(P[i * 3 + 0], -cx);
        float dy = __fadd_rn(P[i * 3 + 1], -cy);
        float dz = __fadd_rn(P[i * 3 + 2], -cz);
        float d2 = __fadd_rn(__fadd_rn(__fmul_rn(dx, dx), __fmul_rn(dy, dy)),
                             __fmul_rn(dz, dz));
        unsigned m = __ballot_sync(0xffffffffu, d2 < R2);
        if (filled == 0 && m) first = basei + __ffs(m) - 1;
        if (d2 < R2) {
            int pos = filled + __popc(m & ((1u << lane) - 1));
            if (pos < NSAMPLE) row[pos] = i;
        }
        filled += __popc(m);
        if (filled >= NSAMPLE) break;
    }
    for (int j = filled + lane; j < NSAMPLE; j += 32) row[j] = first;
}

// ---------------------------------------------------------------------------
// Fused persistent kernel, cluster dims (4,1,1).
// Blocks 0..15: FPS (cluster c = batch c, 4 ranks x 2048 points).
// Blocks 16..127: workers (28 per batch).
// ---------------------------------------------------------------------------
__global__ void __launch_bounds__(TPB, 1) __cluster_dims__(4, 1, 1)
fused_kernel(const float* __restrict__ points,
             const float* __restrict__ features,
             const float* __restrict__ weight,
             float* __restrict__ new_xyz,
             float* __restrict__ conv_out)
{
    extern __shared__ char smraw[];
    __shared__ ull redw[2][TPB / 32];
    __shared__ ull vslots[4];     // tagged candidates, one per rank

    const int t = threadIdx.x;
    const int lane = t & 31;
    const int w = t >> 5;

    if (blockIdx.x < FPS_CTAS) {
        // ======================= FPS role =======================
        const int b = blockIdx.x >> 2;
        const unsigned rank = blockIdx.x & 3;
        float4* pts4 = (float4*)smraw;           // full NPTS copy, 128 KB
        const float* P = points + (size_t)b * NPTS * 3;

        for (int i = t; i < NPTS; i += TPB)
            pts4[i] = make_float4(P[3 * i], P[3 * i + 1], P[3 * i + 2], 0.0f);
        if (t == 0) {
            vslots[0] = 0; vslots[1] = 0; vslots[2] = 0; vslots[3] = 0;
        }
        __syncthreads();
        cluster_barrier();   // slots zeroed + pts loaded in all ranks

        // stage-2 warp = warp 15 (highest arbiter priority); lanes 0..3 write
        // this CTA's candidate into slot[rank] of every rank (incl. self).
        unsigned r_slot = 0;
        if (w == 15 && lane < 4)
            r_slot = mapa_rank(smem_u32(&vslots[rank]), lane);

        volatile ull* vs = (volatile ull*)vslots;

        const int base = rank * QPTS + t * FPPT;
        ull px2[FNPAIR], py2[FNPAIR], pz2[FNPAIR];
        float dist[FPPT];
#pragma unroll
        for (int j = 0; j < FNPAIR; j++) {
            float4 a = pts4[base + 2 * j];
            float4 c = pts4[base + 2 * j + 1];
            px2[j] = f2pk(a.x, c.x);
            py2[j] = f2pk(a.y, c.y);
            pz2[j] = f2pk(a.z, c.z);
        }
#pragma unroll
        for (int j = 0; j < FPPT; j++) dist[j] = 1e10f;

        float4 q0 = pts4[0];
        float lx = q0.x, ly = q0.y, lz = q0.z;
        if (rank == 0 && t == 0) {
            float* o = new_xyz + (size_t)b * NPOINT * 3;
            o[0] = lx; o[1] = ly; o[2] = lz;
        }

        for (int iter = 1; iter < NPOINT; ++iter) {
            const int par = iter & 1;
            const ull lxp = f2pk(lx, lx);
            const ull lyp = f2pk(ly, ly);
            const ull lzp = f2pk(lz, lz);

#pragma unroll
            for (int j = 0; j < FNPAIR; j++) {
                // identical arithmetic to reference: (dx*dx+dy*dy)+dz*dz, rn
                ull dx = f2sub(px2[j], lxp);
                ull dy = f2sub(py2[j], lyp);
                ull dz = f2sub(pz2[j], lzp);
                ull d2 = f2add(f2add(f2mul(dx, dx), f2mul(dy, dy)), f2mul(dz, dz));
                float d0, d1;
                f2unpk(d2, d0, d1);
                dist[2 * j + 0] = fminf(dist[2 * j + 0], d0);
                dist[2 * j + 1] = fminf(dist[2 * j + 1], d1);
            }
            const float bv = fmaxf(fmaxf(dist[0], dist[1]),
                                   fmaxf(dist[2], dist[3]));

            // warp max (dist >= 0 -> uint order == float order)
            const unsigned bb = __float_as_uint(bv);
            const unsigned wm = __reduce_max_sync(0xffffffffu, bb);

            // winner-only rescan (lowest local index matching warp max)
            unsigned li = 0x7fffffffu;
            if (bb == wm) {
#pragma unroll
                for (int j = FPPT - 1; j >= 0; j--)
                    if (__float_as_uint(dist[j]) == wm) li = base + j;
            }
            // lowest lane with bb==wm owns the lowest index (points contiguous)
            const unsigned mk = __ballot_sync(0xffffffffu, bb == wm);
            const int src = __ffs(mk) - 1;
            const unsigned wi_ = __shfl_sync(0xffffffffu, li, src);
            if (lane == 0)
                redw[par][w] = ((ull)wm << 32) | wi_;
            __syncthreads();

            // stage 2 on warp 15 only; other warps fall through to polling
            if (w == 15) {
                const ull v = (lane < TPB / 32) ? redw[par][lane] : 0ull;
                const unsigned hv = (unsigned)(v >> 32);
                const unsigned lv = (unsigned)v;
                const unsigned gmv = __reduce_max_sync(0xffffffffu, hv);
                const unsigned mk2 = __ballot_sync(0xffffffffu, hv == gmv);
                const int s2 = __ffs(mk2) - 1;
                const unsigned lbest = __shfl_sync(0xffffffffu, lv, s2);
                // pack: [iter:19][valbits:32][8191-idx:13] — tag self-verifies,
                // masked compare is exact-max with lowest-index tie-break
                const ull packed = ((ull)iter << 45) | ((ull)gmv << 13)
                                 | (ull)(8191u - lbest);
                if (lane < 4) dsmem_st_u64(r_slot, packed);
            }

            // poll own SMEM until all 4 ranks' candidates carry this iter's tag
            const ull want = (ull)iter;
            ull s0, s1, s2, s3;
            do {
                s0 = vs[0]; s1 = vs[1]; s2 = vs[2]; s3 = vs[3];
            } while ((s0 >> 45) != want || (s1 >> 45) != want ||
                     (s2 >> 45) != want || (s3 >> 45) != want);
            const ull M = ((1ull << 45) - 1);
            const ull mm = umax64(umax64(s0 & M, s1 & M), umax64(s2 & M, s3 & M));
            const int best = 8191 - (int)(mm & 0x1FFFull);

            float4 q = pts4[best];
            lx = q.x; ly = q.y; lz = q.z;
            if (rank == 0 && t == 0) {
                float* o = new_xyz + ((size_t)b * NPOINT + iter) * 3;
                o[0] = lx; o[1] = ly; o[2] = lz;
                if ((iter & 31) == 31)
                    asm volatile("st.release.gpu.global.u32 [%0], %1;"
                                 :: "l"(g_progress + b * 32), "r"(iter + 1) : "memory");
            }
        }
        cluster_barrier();   // keep smem alive until all ranks done
    } else {
        // ======================= worker role =======================
        const int wi = blockIdx.x - FPS_CTAS;    // 0..NWORK-1
        const int b = wi / WPB;
        const int wslot = wi - b * WPB;

        float* s_g   = (float*)smraw;                   // [16][128]
        float* s_w   = s_g + TILE * 128;                // [128][WPAD]
        int*   s_idx = (int*)(s_w + COUT * WPAD);       // [16][32]
        float* s_ctr = (float*)(s_idx + TILE * NSAMPLE);// [16][3]

        const float*  P  = points + (size_t)b * NPTS * 3;
        const float4* F4 = (const float4*)(features + (size_t)b * NPTS * 64);
        const int* flag = g_progress + b * 32;

        // ---------- steady state: 16-center tiles, round-robin ----------
        for (int tile = wslot; tile < TILES16; tile += WPB) {
            const int p0 = tile * TILE;
            wait_progress(flag, p0 + TILE);

            ball_one(P, new_xyz, ((size_t)b * NPOINT + p0 + w) * 3, lane,
                     s_idx + w * NSAMPLE, s_ctr + w * 3);
            __syncthreads();

            const int og = lane;
            const int pg = w;
            const int myidx = s_idx[pg * NSAMPLE + lane];

            float acc[4] = {0.0f, 0.0f, 0.0f, 0.0f};
            for (int chunk = 0; chunk < 17; chunk++) {
                const int c0   = (chunk == 0) ? 0 : (4 * chunk - 1);
                const int kend = (chunk == 0) ? 96 : 128;
                __syncthreads();

                if (chunk == 0) {
#pragma unroll
                    for (int ci = 0; ci < 3; ci++)
                        s_g[pg * 128 + ci * 32 + lane] =
                            P[myidx * 3 + ci] - s_ctr[pg * 3 + ci];
                } else {
                    float4 fv = F4[(size_t)myidx * 16 + (chunk - 1)];
                    s_g[pg * 128 +  0 + lane] = fv.x;
                    s_g[pg * 128 + 32 + lane] = fv.y;
                    s_g[pg * 128 + 64 + lane] = fv.z;
                    s_g[pg * 128 + 96 + lane] = fv.w;
                }
#pragma unroll
                for (int q = 0; q < 8; q++) {
                    const int task = q * TPB + t;
                    const int o = task >> 5;
                    const int k4 = (task & 31) * 4;
                    if (k4 < kend)
                        *(float4*)&s_w[o * WPAD + k4] =
                            *(const float4*)(weight + (size_t)o * KTOT + c0 * 32 + k4);
                }
                __syncthreads();

                for (int kk = 0; kk < kend; kk += 4) {
                    float4 w0 = *(const float4*)&s_w[(og +  0) * WPAD + kk];
                    float4 w1 = *(const float4*)&s_w[(og + 32) * WPAD + kk];
                    float4 w2 = *(const float4*)&s_w[(og + 64) * WPAD + kk];
                    float4 w3 = *(const float4*)&s_w[(og + 96) * WPAD + kk];
                    float4 g  = *(const float4*)&s_g[pg * 128 + kk];
                    acc[0] = fmaf(g.x, w0.x, fmaf(g.y, w0.y, fmaf(g.z, w0.z, fmaf(g.w, w0.w, acc[0]))));
                    acc[1] = fmaf(g.x, w1.x, fmaf(g.y, w1.y, fmaf(g.z, w1.z, fmaf(g.w, w1.w, acc[1]))));
                    acc[2] = fmaf(g.x, w2.x, fmaf(g.y, w2.y, fmaf(g.z, w2.z, fmaf(g.w, w2.w, acc[2]))));
                    acc[3] = fmaf(g.x, w3.x, fmaf(g.y, w3.y, fmaf(g.z, w3.z, fmaf(g.w, w3.w, acc[3]))));
                }
            }

            float* dst = conv_out + ((size_t)b * NPOINT + p0 + pg) * COUT;
            dst[og +  0] = acc[0];
            dst[og + 32] = acc[1];
            dst[og + 64] = acc[2];
            dst[og + 96] = acc[3];
            __syncthreads();
        }

        // ---------- tail: one 4-center minitile per worker ----------
        if (wslot < NMINI) {
            const int p0 = MINI_BASE + wslot * 4;
            wait_progress(flag, p0 + 4);

            if (w < 4)
                ball_one(P, new_xyz, ((size_t)b * NPOINT + p0 + w) * 3, lane,
                         s_idx + w * NSAMPLE, s_ctr + w * 3);
            __syncthreads();

            const int o = t & 127;          // one output per thread
            const int p = t >> 7;           // one point per thread
            const int myidx = (t < 128) ? s_idx[(t >> 5) * NSAMPLE + lane] : 0;

            float acc = 0.0f;
            for (int chunk = 0; chunk < 17; chunk++) {
                const int c0   = (chunk == 0) ? 0 : (4 * chunk - 1);
                const int kend = (chunk == 0) ? 96 : 128;
                __syncthreads();

                if (t < 128) {
                    const int pp = t >> 5;
                    if (chunk == 0) {
#pragma unroll
                        for (int ci = 0; ci < 3; ci++)
                            s_g[pp * 128 + ci * 32 + lane] =
                                P[myidx * 3 + ci] - s_ctr[pp * 3 + ci];
                    } else {
                        float4 fv = F4[(size_t)myidx * 16 + (chunk - 1)];
                        s_g[pp * 128 +  0 + lane] = fv.x;
                        s_g[pp * 128 + 32 + lane] = fv.y;
                        s_g[pp * 128 + 64 + lane] = fv.z;
                        s_g[pp * 128 + 96 + lane] = fv.w;
                    }
                }
#pragma unroll
                for (int q = 0; q < 8; q++) {
                    const int task = q * TPB + t;
                    const int oo = task >> 5;
                    const int k4 = (task & 31) * 4;
                    if (k4 < kend)
                        *(float4*)&s_w[oo * WPAD + k4] =
                            *(const float4*)(weight + (size_t)oo * KTOT + c0 * 32 + k4);
                }
                __syncthreads();

                for (int kk = 0; kk < kend; kk += 4) {
                    float4 wv = *(const float4*)&s_w[o * WPAD + kk];
                    float4 g  = *(const float4*)&s_g[p * 128 + kk];
                    acc = fmaf(g.x, wv.x, fmaf(g.y, wv.y, fmaf(g.z, wv.z, fmaf(g.w, wv.w, acc))));
                }
            }
            conv_out[((size_t)b * NPOINT + p0 + p) * COUT + o] = acc;
        }
    }
}

// ---------------------------------------------------------------------------

extern "C" void kernel_launch(void* const* d_in, const int* in_sizes, int n_in,
                              void* d_out, int out_size)
{
    const float* points   = (const float*)d_in[0];
    const float* features = (const float*)d_in[1];
    const float* weight   = (const float*)d_in[2];
    float* out = (float*)d_out;
    float* new_xyz = out;                            // B*NPOINT*3
    float* conv    = out + BATCH * NPOINT * 3;       // B*NPOINT*COUT

    const int smem = NPTS * sizeof(float4);          // 128 KB
    cudaFuncSetAttribute(fused_kernel, cudaFuncAttributeMaxDynamicSharedMemorySize, smem);

    reset_kernel<<<1, 128>>>();
    fused_kernel<<<FPS_CTAS + NWORK, TPB, smem>>>(points, features, weight, new_xyz, conv);
}

// round 10
// speedup vs baseline: 1.6432x; 1.1533x over previous
#include <cuda_runtime.h>

#define NPTS    8192
#define BATCH   4
#define NPOINT  2048
#define NSAMPLE 32
#define CIN     67
#define COUT    128
#define KTOT    (CIN * NSAMPLE)   // 2144
#define R2      0.04f

#define TPB     512

// FPS: 4 CTAs (one cluster) per batch
#define FPS_CTAS 16               // 4 batches x 4 ranks
#define QPTS    2048              // points per FPS rank
#define FPPT    (QPTS / TPB)      // 4 points per thread
#define FNPAIR  (FPPT / 2)        // 2 packed pairs

#define WPB     28                // worker CTAs per batch
#define NWORK   (WPB * BATCH)     // 112 workers (total grid 128 <= 132 cap)
#define TILE    16                // centers per steady-state conv tile
#define TILES16 121               // 16-center tiles per batch (centers 0..1936)
#define MINI_BASE 1936            // final 112 centers -> 28 minitiles of 4
#define NMINI   28
#define WPAD    132               // s_w row pitch (132 % 32 == 4 -> conflict-free)

typedef unsigned long long ull;

// progress flags: one 128B line per batch
__device__ int g_progress[BATCH * 32];

// ---------------------------------------------------------------------------
// packed f32x2 helpers (sm_103a) — add/sub/mul only
// ---------------------------------------------------------------------------
__device__ __forceinline__ ull f2pk(float lo, float hi) {
    ull r; asm("mov.b64 %0, {%1, %2};" : "=l"(r) : "f"(lo), "f"(hi)); return r;
}
__device__ __forceinline__ void f2unpk(ull v, float& lo, float& hi) {
    asm("mov.b64 {%0, %1}, %2;" : "=f"(lo), "=f"(hi) : "l"(v));
}
__device__ __forceinline__ ull f2add(ull a, ull b) {
    ull r; asm("add.rn.f32x2 %0, %1, %2;" : "=l"(r) : "l"(a), "l"(b)); return r;
}
__device__ __forceinline__ ull f2sub(ull a, ull b) {
    ull r; asm("sub.rn.f32x2 %0, %1, %2;" : "=l"(r) : "l"(a), "l"(b)); return r;
}
__device__ __forceinline__ ull f2mul(ull a, ull b) {
    ull r; asm("mul.rn.f32x2 %0, %1, %2;" : "=l"(r) : "l"(a), "l"(b)); return r;
}
__device__ __forceinline__ ull umax64(ull a, ull b) { return a > b ? a : b; }

// ---------------------------------------------------------------------------
// cluster helpers (no mbarriers — tagged-slot polling, poller = warp 15 only)
// ---------------------------------------------------------------------------
__device__ __forceinline__ unsigned smem_u32(const void* p) {
    unsigned a;
    asm("{ .reg .u64 t; cvta.to.shared.u64 t, %1; cvt.u32.u64 %0, t; }"
        : "=r"(a) : "l"(p));
    return a;
}
__device__ __forceinline__ unsigned mapa_rank(unsigned addr, unsigned r) {
    unsigned d;
    asm("mapa.shared::cluster.u32 %0, %1, %2;" : "=r"(d) : "r"(addr), "r"(r));
    return d;
}
__device__ __forceinline__ void dsmem_st_u64(unsigned addr, ull v) {
    asm volatile("st.shared::cluster.u64 [%0], %1;" :: "r"(addr), "l"(v) : "memory");
}
__device__ __forceinline__ void cluster_barrier() {
    asm volatile("barrier.cluster.arrive.aligned;" ::: "memory");
    asm volatile("barrier.cluster.wait.aligned;" ::: "memory");
}

__global__ void reset_kernel() {
    if (threadIdx.x < BATCH * 32) g_progress[threadIdx.x] = 0;
}

// ---------------------------------------------------------------------------
// worker helpers
// ---------------------------------------------------------------------------
__device__ __forceinline__ void wait_progress(const int* flag, int target) {
    if (threadIdx.x == 0) {
        unsigned pr;
        while (true) {
            asm volatile("ld.acquire.gpu.global.u32 %0, [%1];"
                         : "=r"(pr) : "l"(flag) : "memory");
            if ((int)pr >= target) break;
            __nanosleep(256);
        }
    }
    __syncthreads();
}

__device__ __forceinline__ void ball_one(const float* __restrict__ P,
                                         const float* __restrict__ nx,
                                         size_t crow, int lane,
                                         int* row, float* ctr3)
{
    const float cx = nx[crow + 0];
    const float cy = nx[crow + 1];
    const float cz = nx[crow + 2];
    if (lane < 3) ctr3[lane] = nx[crow + lane];

    int filled = 0, first = 0;
    for (int basei = 0; basei < NPTS; basei += 32) {
        const int i = basei + lane;
        float dx = __fadd_rn(P[i * 3 + 0], -cx);
        float dy = __fadd_rn(P[i * 3 + 1], -cy);
        float dz = __fadd_rn(P[i * 3 + 2], -cz);
        float d2 = __fadd_rn(__fadd_rn(__fmul_rn(dx, dx), __fmul_rn(dy, dy)),
                             __fmul_rn(dz, dz));
        unsigned m = __ballot_sync(0xffffffffu, d2 < R2);
        if (filled == 0 && m) first = basei + __ffs(m) - 1;
        if (d2 < R2) {
            int pos = filled + __popc(m & ((1u << lane) - 1));
            if (pos < NSAMPLE) row[pos] = i;
        }
        filled += __popc(m);
        if (filled >= NSAMPLE) break;
    }
    for (int j = filled + lane; j < NSAMPLE; j += 32) row[j] = first;
}

// ---------------------------------------------------------------------------
// Fused persistent kernel, cluster dims (4,1,1).
// Blocks 0..15: FPS (cluster c = batch c, 4 ranks x 2048 points).
// Blocks 16..127: workers (28 per batch).
// ---------------------------------------------------------------------------
__global__ void __launch_bounds__(TPB, 1) __cluster_dims__(4, 1, 1)
fused_kernel(const float* __restrict__ points,
             const float* __restrict__ features,
             const float* __restrict__ weight,
             float* __restrict__ new_xyz,
             float* __restrict__ conv_out)
{
    extern __shared__ char smraw[];
    __shared__ ull redw[2][TPB / 32];
    __shared__ ull vslots[4];     // tagged candidates, one per rank
    __shared__ int s_best[2];     // parity double-buffered winner index

    const int t = threadIdx.x;
    const int lane = t & 31;
    const int w = t >> 5;

    if (blockIdx.x < FPS_CTAS) {
        // ======================= FPS role =======================
        const int b = blockIdx.x >> 2;
        const unsigned rank = blockIdx.x & 3;
        float4* pts4 = (float4*)smraw;           // full NPTS copy, 128 KB
        const float* P = points + (size_t)b * NPTS * 3;

        for (int i = t; i < NPTS; i += TPB)
            pts4[i] = make_float4(P[3 * i], P[3 * i + 1], P[3 * i + 2], 0.0f);
        if (t == 0) {
            vslots[0] = 0; vslots[1] = 0; vslots[2] = 0; vslots[3] = 0;
        }
        __syncthreads();
        cluster_barrier();   // slots zeroed + pts loaded in all ranks

        // warp 15 = exchange warp (highest arbiter priority).
        // lanes 0..3 write this CTA's candidate into slot[rank] of every rank.
        unsigned r_slot = 0;
        if (w == 15 && lane < 4)
            r_slot = mapa_rank(smem_u32(&vslots[rank]), lane);

        volatile ull* vs = (volatile ull*)vslots;

        const int base = rank * QPTS + t * FPPT;
        ull px2[FNPAIR], py2[FNPAIR], pz2[FNPAIR];
        float dist[FPPT];
#pragma unroll
        for (int j = 0; j < FNPAIR; j++) {
            float4 a = pts4[base + 2 * j];
            float4 c = pts4[base + 2 * j + 1];
            px2[j] = f2pk(a.x, c.x);
            py2[j] = f2pk(a.y, c.y);
            pz2[j] = f2pk(a.z, c.z);
        }
#pragma unroll
        for (int j = 0; j < FPPT; j++) dist[j] = 1e10f;

        float4 q0 = pts4[0];
        float lx = q0.x, ly = q0.y, lz = q0.z;
        if (rank == 0 && t == 0) {
            float* o = new_xyz + (size_t)b * NPOINT * 3;
            o[0] = lx; o[1] = ly; o[2] = lz;
        }

        for (int iter = 1; iter < NPOINT; ++iter) {
            const int par = iter & 1;
            const ull lxp = f2pk(lx, lx);
            const ull lyp = f2pk(ly, ly);
            const ull lzp = f2pk(lz, lz);

#pragma unroll
            for (int j = 0; j < FNPAIR; j++) {
                // identical arithmetic to reference: (dx*dx+dy*dy)+dz*dz, rn
                ull dx = f2sub(px2[j], lxp);
                ull dy = f2sub(py2[j], lyp);
                ull dz = f2sub(pz2[j], lzp);
                ull d2 = f2add(f2add(f2mul(dx, dx), f2mul(dy, dy)), f2mul(dz, dz));
                float d0, d1;
                f2unpk(d2, d0, d1);
                dist[2 * j + 0] = fminf(dist[2 * j + 0], d0);
                dist[2 * j + 1] = fminf(dist[2 * j + 1], d1);
            }
            const float bv = fmaxf(fmaxf(dist[0], dist[1]),
                                   fmaxf(dist[2], dist[3]));

            // stage 1: warp max (dist >= 0 -> uint order == float order)
            const unsigned bb = __float_as_uint(bv);
            const unsigned wm = __reduce_max_sync(0xffffffffu, bb);

            unsigned li = 0x7fffffffu;
            if (bb == wm) {
#pragma unroll
                for (int j = FPPT - 1; j >= 0; j--)
                    if (__float_as_uint(dist[j]) == wm) li = base + j;
            }
            const unsigned mk = __ballot_sync(0xffffffffu, bb == wm);
            const int src = __ffs(mk) - 1;
            const unsigned wi_ = __shfl_sync(0xffffffffu, li, src);
            if (lane == 0)
                redw[par][w] = ((ull)wm << 32) | wi_;
            __syncthreads();                       // bar A

            // stage 2 + exchange + poll: warp 15 ONLY (others park at bar B,
            // keeping the LSU/smem port free for the critical path)
            if (w == 15) {
                const ull v = (lane < TPB / 32) ? redw[par][lane] : 0ull;
                const unsigned hv = (unsigned)(v >> 32);
                const unsigned lv = (unsigned)v;
                const unsigned gmv = __reduce_max_sync(0xffffffffu, hv);
                const unsigned mk2 = __ballot_sync(0xffffffffu, hv == gmv);
                const int s2i = __ffs(mk2) - 1;
                const unsigned lbest = __shfl_sync(0xffffffffu, lv, s2i);
                // pack: [iter:19][valbits:32][8191-idx:13] — tag self-verifies,
                // masked compare = exact max with lowest-index tie-break
                const ull packed = ((ull)iter << 45) | ((ull)gmv << 13)
                                 | (ull)(8191u - lbest);
                if (lane < 4) dsmem_st_u64(r_slot, packed);

                // poll own SMEM for all 4 ranks' tags (32 threads only)
                const ull want = (ull)iter;
                ull s0, s1, s2, s3;
                do {
                    s0 = vs[0]; s1 = vs[1]; s2 = vs[2]; s3 = vs[3];
                } while ((s0 >> 45) != want || (s1 >> 45) != want ||
                         (s2 >> 45) != want || (s3 >> 45) != want);
                const ull M = ((1ull << 45) - 1);
                const ull mm = umax64(umax64(s0 & M, s1 & M),
                                      umax64(s2 & M, s3 & M));
                if (lane == 0) s_best[par] = 8191 - (int)(mm & 0x1FFFull);
            }
            __syncthreads();                       // bar B (released by warp 15)

            const int best = s_best[par];
            float4 q = pts4[best];
            lx = q.x; ly = q.y; lz = q.z;
            if (rank == 0 && t == 0) {
                float* o = new_xyz + ((size_t)b * NPOINT + iter) * 3;
                o[0] = lx; o[1] = ly; o[2] = lz;
                if ((iter & 31) == 31)
                    asm volatile("st.release.gpu.global.u32 [%0], %1;"
                                 :: "l"(g_progress + b * 32), "r"(iter + 1) : "memory");
            }
        }
        cluster_barrier();   // keep smem alive until all ranks done
    } else {
        // ======================= worker role =======================
        const int wi = blockIdx.x - FPS_CTAS;    // 0..NWORK-1
        const int b = wi / WPB;
        const int wslot = wi - b * WPB;

        float* s_g   = (float*)smraw;                   // [16][128]
        float* s_w   = s_g + TILE * 128;                // [128][WPAD]
        int*   s_idx = (int*)(s_w + COUT * WPAD);       // [16][32]
        float* s_ctr = (float*)(s_idx + TILE * NSAMPLE);// [16][3]

        const float*  P  = points + (size_t)b * NPTS * 3;
        const float4* F4 = (const float4*)(features + (size_t)b * NPTS * 64);
        const int* flag = g_progress + b * 32;

        // ---------- steady state: 16-center tiles, round-robin ----------
        for (int tile = wslot; tile < TILES16; tile += WPB) {
            const int p0 = tile * TILE;
            wait_progress(flag, p0 + TILE);

            ball_one(P, new_xyz, ((size_t)b * NPOINT + p0 + w) * 3, lane,
                     s_idx + w * NSAMPLE, s_ctr + w * 3);
            __syncthreads();

            const int og = lane;
            const int pg = w;
            const int myidx = s_idx[pg * NSAMPLE + lane];

            float acc[4] = {0.0f, 0.0f, 0.0f, 0.0f};
            for (int chunk = 0; chunk < 17; chunk++) {
                const int c0   = (chunk == 0) ? 0 : (4 * chunk - 1);
                const int kend = (chunk == 0) ? 96 : 128;
                __syncthreads();

                if (chunk == 0) {
#pragma unroll
                    for (int ci = 0; ci < 3; ci++)
                        s_g[pg * 128 + ci * 32 + lane] =
                            P[myidx * 3 + ci] - s_ctr[pg * 3 + ci];
                } else {
                    float4 fv = F4[(size_t)myidx * 16 + (chunk - 1)];
                    s_g[pg * 128 +  0 + lane] = fv.x;
                    s_g[pg * 128 + 32 + lane] = fv.y;
                    s_g[pg * 128 + 64 + lane] = fv.z;
                    s_g[pg * 128 + 96 + lane] = fv.w;
                }
#pragma unroll
                for (int q = 0; q < 8; q++) {
                    const int task = q * TPB + t;
                    const int o = task >> 5;
                    const int k4 = (task & 31) * 4;
                    if (k4 < kend)
                        *(float4*)&s_w[o * WPAD + k4] =
                            *(const float4*)(weight + (size_t)o * KTOT + c0 * 32 + k4);
                }
                __syncthreads();

                for (int kk = 0; kk < kend; kk += 4) {
                    float4 w0 = *(const float4*)&s_w[(og +  0) * WPAD + kk];
                    float4 w1 = *(const float4*)&s_w[(og + 32) * WPAD + kk];
                    float4 w2 = *(const float4*)&s_w[(og + 64) * WPAD + kk];
                    float4 w3 = *(const float4*)&s_w[(og + 96) * WPAD + kk];
                    float4 g  = *(const float4*)&s_g[pg * 128 + kk];
                    acc[0] = fmaf(g.x, w0.x, fmaf(g.y, w0.y, fmaf(g.z, w0.z, fmaf(g.w, w0.w, acc[0]))));
                    acc[1] = fmaf(g.x, w1.x, fmaf(g.y, w1.y, fmaf(g.z, w1.z, fmaf(g.w, w1.w, acc[1]))));
                    acc[2] = fmaf(g.x, w2.x, fmaf(g.y, w2.y, fmaf(g.z, w2.z, fmaf(g.w, w2.w, acc[2]))));
                    acc[3] = fmaf(g.x, w3.x, fmaf(g.y, w3.y, fmaf(g.z, w3.z, fmaf(g.w, w3.w, acc[3]))));
                }
            }

            float* dst = conv_out + ((size_t)b * NPOINT + p0 + pg) * COUT;
            dst[og +  0] = acc[0];
            dst[og + 32] = acc[1];
            dst[og + 64] = acc[2];
            dst[og + 96] = acc[3];
            __syncthreads();
        }

        // ---------- tail: one 4-center minitile per worker ----------
        if (wslot < NMINI) {
            const int p0 = MINI_BASE + wslot * 4;
            wait_progress(flag, p0 + 4);

            if (w < 4)
                ball_one(P, new_xyz, ((size_t)b * NPOINT + p0 + w) * 3, lane,
                         s_idx + w * NSAMPLE, s_ctr + w * 3);
            __syncthreads();

            const int o = t & 127;          // one output per thread
            const int p = t >> 7;           // one point per thread
            const int myidx = (t < 128) ? s_idx[(t >> 5) * NSAMPLE + lane] : 0;

            float acc = 0.0f;
            for (int chunk = 0; chunk < 17; chunk++) {
                const int c0   = (chunk == 0) ? 0 : (4 * chunk - 1);
                const int kend = (chunk == 0) ? 96 : 128;
                __syncthreads();

                if (t < 128) {
                    const int pp = t >> 5;
                    if (chunk == 0) {
#pragma unroll
                        for (int ci = 0; ci < 3; ci++)
                            s_g[pp * 128 + ci * 32 + lane] =
                                P[myidx * 3 + ci] - s_ctr[pp * 3 + ci];
                    } else {
                        float4 fv = F4[(size_t)myidx * 16 + (chunk - 1)];
                        s_g[pp * 128 +  0 + lane] = fv.x;
                        s_g[pp * 128 + 32 + lane] = fv.y;
                        s_g[pp * 128 + 64 + lane] = fv.z;
                        s_g[pp * 128 + 96 + lane] = fv.w;
                    }
                }
#pragma unroll
                for (int q = 0; q < 8; q++) {
                    const int task = q * TPB + t;
                    const int oo = task >> 5;
                    const int k4 = (task & 31) * 4;
                    if (k4 < kend)
                        *(float4*)&s_w[oo * WPAD + k4] =
                            *(const float4*)(weight + (size_t)oo * KTOT + c0 * 32 + k4);
                }
                __syncthreads();

                for (int kk = 0; kk < kend; kk += 4) {
                    float4 wv = *(const float4*)&s_w[o * WPAD + kk];
                    float4 g  = *(const float4*)&s_g[p * 128 + kk];
                    acc = fmaf(g.x, wv.x, fmaf(g.y, wv.y, fmaf(g.z, wv.z, fmaf(g.w, wv.w, acc))));
                }
            }
            conv_out[((size_t)b * NPOINT + p0 + p) * COUT + o] = acc;
        }
    }
}

// ---------------------------------------------------------------------------

extern "C" void kernel_launch(void* const* d_in, const int* in_sizes, int n_in,
                              void* d_out, int out_size)
{
    const float* points   = (const float*)d_in[0];
    const float* features = (const float*)d_in[1];
    const float* weight   = (const float*)d_in[2];
    float* out = (float*)d_out;
    float* new_xyz = out;                            // B*NPOINT*3
    float* conv    = out + BATCH * NPOINT * 3;       // B*NPOINT*COUT

    const int smem = NPTS * sizeof(float4);          // 128 KB
    cudaFuncSetAttribute(fused_kernel, cudaFuncAttributeMaxDynamicSharedMemorySize, smem);

    reset_kernel<<<1, 128>>>();
    fused_kernel<<<FPS_CTAS + NWORK, TPB, smem>>>(points, features, weight, new_xyz, conv);
}